// round 1
// baseline (speedup 1.0000x reference)
#include <cuda_runtime.h>
#include <cuda_bf16.h>

#define NN 4
#define CC 256
#define HH 64
#define WW 64
#define CM 64
#define K2 25
#define D2 4
#define HW (HH*WW)          // 4096
#define HW2 (4*HW)          // 16384 pixels per image after 2x upsample

// Scratch (device globals; allocation-free per harness rules)
__device__ float g_t[NN*CM*HW];            // 1,048,576 floats (4 MB)
__device__ float g_kern[NN*HW*K2*D2];      // 1,638,400 floats (6.5 MB), layout [n][h][w][k][p]
__device__ float g_mid[NN*CC*HW2];         // 16,777,216 floats (67 MB), NCHW at (2H,2W)

// ---------------------------------------------------------------------------
// Kernel 1: 1x1 down conv.  t[n,m,h,w] = sum_c x[n,c,h,w]*Wd[m,c] + bd[m]
// grid 128 blocks x 128 threads; each block = 128 consecutive (n,hw) pixels.
// ---------------------------------------------------------------------------
__global__ void k_down(const float* __restrict__ x, const float* __restrict__ Wd,
                       const float* __restrict__ bd, float* __restrict__ t) {
    __shared__ float sw[128*64];   // [c_local][m], 32 KB
    int tid = threadIdx.x;
    int base = blockIdx.x * 128;
    int n = base >> 12;
    int hw = (base & 4095) + tid;
    const float* xp = x + (size_t)n*CC*HW + hw;

    float acc[64];
#pragma unroll
    for (int m = 0; m < 64; m++) acc[m] = bd[m];

    for (int c0 = 0; c0 < 256; c0 += 128) {
        __syncthreads();
        for (int i = tid; i < 128*64; i += 128) {
            int cl = i & 127;
            int m  = i >> 7;
            sw[cl*64 + m] = Wd[m*256 + c0 + cl];
        }
        __syncthreads();
        for (int cl = 0; cl < 128; cl++) {
            float xv = xp[(size_t)(c0 + cl) * HW];
            const float4* w4 = (const float4*)(sw + cl*64);
#pragma unroll
            for (int q = 0; q < 16; q++) {
                float4 wv = w4[q];
                acc[4*q+0] += xv*wv.x; acc[4*q+1] += xv*wv.y;
                acc[4*q+2] += xv*wv.z; acc[4*q+3] += xv*wv.w;
            }
        }
    }
    float* tp = t + (size_t)n*CM*HW + hw;
#pragma unroll
    for (int m = 0; m < 64; m++) tp[(size_t)m*HW] = acc[m];
}

// ---------------------------------------------------------------------------
// Kernel 2: 3x3 encoder conv (100 out ch) + per-pixel softmax over K2=25.
// Block = (n,h); threads (w=64, p=4). Thread (w,p) computes e[n, k*4+p, h, w]
// for all k -> softmax over k done fully in registers.
// kern layout out: [n][h][w][k][p]
// ---------------------------------------------------------------------------
__global__ void k_enc(const float* __restrict__ t, const float* __restrict__ We,
                      const float* __restrict__ be, float* __restrict__ kern) {
    __shared__ float st[8*3*68];        // [ml][r][ww], halo 1 each side (cols 0..65 valid)
    __shared__ float swt[8*9*4*28];     // [ml][tap][p][k(pad28)]
    int w = threadIdx.x;
    int p = threadIdx.y;
    int tid = p*64 + w;
    int n = blockIdx.x >> 6;
    int h = blockIdx.x & 63;
    const float* tb = t + (size_t)n*CM*HW;

    float acc[28];
#pragma unroll
    for (int k = 0; k < 28; k++) acc[k] = 0.f;

    for (int m0 = 0; m0 < 64; m0 += 8) {
        __syncthreads();
        // stage t tile: rows h-1..h+1, channels m0..m0+7, cols with halo
        for (int i = tid; i < 8*3*68; i += 256) {
            int ml = i / 204;
            int r  = (i / 68) % 3;
            int ww = i % 68;
            int hh = h + r - 1;
            int wx = ww - 1;
            float v = 0.f;
            if (hh >= 0 && hh < 64 && wx >= 0 && wx < 64)
                v = tb[(size_t)(m0+ml)*HW + hh*64 + wx];
            st[i] = v;
        }
        // stage weights transposed: swt[((ml*9+tap)*4+p)*28 + k] = We[(k*4+p)*576 + (m0+ml)*9 + tap]
        for (int i = tid; i < 8*9*4*28; i += 256) {
            int k   = i % 28;
            int pp  = (i / 28) % 4;
            int tap = (i / 112) % 9;
            int ml  = i / 1008;
            float v = 0.f;
            if (k < 25) v = We[(k*4+pp)*576 + (m0+ml)*9 + tap];
            swt[i] = v;
        }
        __syncthreads();

        for (int ml = 0; ml < 8; ml++) {
#pragma unroll
            for (int tap = 0; tap < 9; tap++) {
                int di = tap / 3, dj = tap % 3;
                float tv = st[ml*204 + di*68 + (w + dj)];  // col (w+dj-1)+1
                const float4* wp = (const float4*)(swt + ((ml*9 + tap)*4 + p)*28);
#pragma unroll
                for (int q = 0; q < 7; q++) {
                    float4 wv = wp[q];
                    acc[4*q+0] += tv*wv.x; acc[4*q+1] += tv*wv.y;
                    acc[4*q+2] += tv*wv.z; acc[4*q+3] += tv*wv.w;
                }
            }
        }
    }

    // softmax over k = 0..24 (bias added first)
    float mx = -1e30f;
#pragma unroll
    for (int k = 0; k < 25; k++) {
        acc[k] += be[k*4 + p];
        mx = fmaxf(mx, acc[k]);
    }
    float s = 0.f;
#pragma unroll
    for (int k = 0; k < 25; k++) {
        acc[k] = __expf(acc[k] - mx);
        s += acc[k];
    }
    float inv = 1.f / s;
    float* kp = kern + ((size_t)(n*HW + h*64 + w) * 25) * 4 + p;
#pragma unroll
    for (int k = 0; k < 25; k++) kp[k*4] = acc[k] * inv;
}

// ---------------------------------------------------------------------------
// Kernel 3: content-aware reassembly + pixel shuffle.
// mid[n,c,2h+i,2w+j] = sum_k x_pad[n,c,h+ki-2,w+kj-2] * kern[n,h,w,k,(i*2+j)]
// Block = (n,h); threads (w=64, cg=4). c chunked by 32; thread owns 8 c, 4 p.
// Dynamic smem: sk[25][64][4] + sx[32][5][68]  (69120 B)
// ---------------------------------------------------------------------------
__global__ void k_reasm(const float* __restrict__ x, const float* __restrict__ kern,
                        float* __restrict__ mid) {
    extern __shared__ float smem[];
    float* sk = smem;              // [k][w][p]: k*256 + w*4 + p   (6400 floats)
    float* sx = smem + 25*64*4;    // [cl][r][ww]: cl*340 + r*68 + ww (10880 floats)

    int w  = threadIdx.x;
    int cg = threadIdx.y;
    int tid = cg*64 + w;
    int n = blockIdx.x >> 6;
    int h = blockIdx.x & 63;

    // stage kern for this (n,h) row, transposed to [k][w][p]
    const float* kb = kern + (size_t)(n*HW + h*64) * 100;
    for (int i = tid; i < 6400; i += 256) {
        int ww = i / 100;
        int r  = i % 100;          // r = k*4 + p
        int k  = r >> 2;
        int pp = r & 3;
        sk[k*256 + ww*4 + pp] = kb[ww*100 + r];
    }

    for (int c0 = 0; c0 < 256; c0 += 32) {
        __syncthreads();
        // stage x tile: rows h-2..h+2, 32 channels, cols -2..65 (zero padded)
        for (int i = tid; i < 32*5*68; i += 256) {
            int cl = i / 340;
            int r  = (i / 68) % 5;
            int ww = i % 68;
            int hh = h + r - 2;
            int wx = ww - 2;
            float v = 0.f;
            if (hh >= 0 && hh < 64 && wx >= 0 && wx < 64)
                v = x[((size_t)(n*CC + c0 + cl) * 64 + hh) * 64 + wx];
            sx[i] = v;
        }
        __syncthreads();

        float acc[8][4];
#pragma unroll
        for (int cc = 0; cc < 8; cc++)
#pragma unroll
            for (int q = 0; q < 4; q++) acc[cc][q] = 0.f;

        int cl0 = cg * 8;
#pragma unroll
        for (int k = 0; k < 25; k++) {
            int ki = k / 5, kj = k % 5;
            float4 kv = *(const float4*)(sk + k*256 + w*4);
#pragma unroll
            for (int cc = 0; cc < 8; cc++) {
                float xv = sx[(cl0+cc)*340 + ki*68 + (w + kj)];
                acc[cc][0] += xv*kv.x; acc[cc][1] += xv*kv.y;
                acc[cc][2] += xv*kv.z; acc[cc][3] += xv*kv.w;
            }
        }

        // write mid (NCHW at 2H x 2W); p = i*2 + j
#pragma unroll
        for (int cc = 0; cc < 8; cc++) {
            int c = c0 + cl0 + cc;
            float* mp = mid + ((size_t)(n*CC + c) * 128 + 2*h) * 128 + 2*w;
            float2 v0 = make_float2(acc[cc][0], acc[cc][1]);
            float2 v1 = make_float2(acc[cc][2], acc[cc][3]);
            *(float2*)(mp)       = v0;
            *(float2*)(mp + 128) = v1;
        }
    }
}

// ---------------------------------------------------------------------------
// Kernel 4: final 1x1 conv = GEMM  out[n,o,pix] = sum_c Wo[o,c]*mid[n,c,pix] + bo[o]
// grid (pix/128, o/64, n), block 256. Block tile 128pix x 64o, thread 4pix x 8o.
// ---------------------------------------------------------------------------
__global__ void k_out(const float* __restrict__ mid, const float* __restrict__ Wo,
                      const float* __restrict__ bo, float* __restrict__ out) {
    __shared__ float sA[16][64];    // [cl][o]
    __shared__ float sB[16][128];   // [cl][pix]
    int tid = threadIdx.x;
    int tx = tid & 31;              // pix group: pix = tx*4
    int ty = tid >> 5;              // o group:   o  = ty*8
    int pix0 = blockIdx.x * 128;
    int o0   = blockIdx.y * 64;
    int n    = blockIdx.z;
    const float* mb = mid + (size_t)n*CC*HW2 + pix0;

    float acc[8][4];
#pragma unroll
    for (int oo = 0; oo < 8; oo++)
#pragma unroll
        for (int q = 0; q < 4; q++) acc[oo][q] = 0.f;

    for (int c0 = 0; c0 < 256; c0 += 16) {
        __syncthreads();
        for (int i = tid; i < 1024; i += 256) {
            int cl = i & 15, ol = i >> 4;
            sA[cl][ol] = Wo[(o0+ol)*256 + c0 + cl];
        }
        for (int i = tid; i < 2048; i += 256) {
            int px = i & 127, cl = i >> 7;
            sB[cl][px] = mb[(size_t)(c0+cl)*HW2 + px];
        }
        __syncthreads();
#pragma unroll
        for (int cl = 0; cl < 16; cl++) {
            float4 bv = *(const float4*)(&sB[cl][tx*4]);
            float a[8];
            *(float4*)(a)   = *(const float4*)(&sA[cl][ty*8]);
            *(float4*)(a+4) = *(const float4*)(&sA[cl][ty*8+4]);
#pragma unroll
            for (int oo = 0; oo < 8; oo++) {
                acc[oo][0] += a[oo]*bv.x; acc[oo][1] += a[oo]*bv.y;
                acc[oo][2] += a[oo]*bv.z; acc[oo][3] += a[oo]*bv.w;
            }
        }
    }
#pragma unroll
    for (int oo = 0; oo < 8; oo++) {
        int o = o0 + ty*8 + oo;
        float b = bo[o];
        float4 v = make_float4(acc[oo][0]+b, acc[oo][1]+b, acc[oo][2]+b, acc[oo][3]+b);
        *(float4*)(out + ((size_t)(n*CC + o) * HW2) + pix0 + tx*4) = v;
    }
}

// ---------------------------------------------------------------------------
extern "C" void kernel_launch(void* const* d_in, const int* in_sizes, int n_in,
                              void* d_out, int out_size) {
    const float* x   = (const float*)d_in[0];
    const float* Wd  = (const float*)d_in[1];
    const float* bd  = (const float*)d_in[2];
    const float* We  = (const float*)d_in[3];
    const float* be  = (const float*)d_in[4];
    const float* Wo  = (const float*)d_in[5];
    const float* bo  = (const float*)d_in[6];
    float* out = (float*)d_out;

    float *t, *kern, *mid;
    cudaGetSymbolAddress((void**)&t,    g_t);
    cudaGetSymbolAddress((void**)&kern, g_kern);
    cudaGetSymbolAddress((void**)&mid,  g_mid);

    // opt-in dynamic smem for k_reasm (69120 B > 48 KB default)
    cudaFuncSetAttribute(k_reasm, cudaFuncAttributeMaxDynamicSharedMemorySize, 69120);

    k_down<<<128, 128>>>(x, Wd, bd, t);
    k_enc<<<NN*HH, dim3(64,4)>>>(t, We, be, kern);
    k_reasm<<<NN*HH, dim3(64,4), 69120>>>(x, kern, mid);
    k_out<<<dim3(128, 4, NN), 256>>>(mid, Wo, bo, out);
}

// round 5
// speedup vs baseline: 1.9014x; 1.9014x over previous
#include <cuda_runtime.h>
#include <cuda_bf16.h>

#define NN 4
#define CC 256
#define HH 64
#define WW 64
#define CM 64
#define K2 25
#define HW (HH*WW)          // 4096

// Scratch (device globals; allocation-free per harness rules)
__device__ float g_t[NN*CM*HW];            // 4 MB:  down-projected features
__device__ float g_kern[NN*HW*K2*4];       // 6.5 MB: [n][h][w][k][p]
__device__ float g_y[NN*CC*HW];            // 16 MB: y = W_out * x (low-res!)

// ---------------------------------------------------------------------------
// Generic tiled fp32 GEMM over pixels:  Y[n,m,pix] = sum_c Wm[m,c]*X[n,c,pix] (+b[m])
// X layout [n][256][HW]. Block tile BM x 128pix, K-step 16, thread tile TM x TP.
// ---------------------------------------------------------------------------
template<int BM, int TM, int TP, bool BIAS>
__global__ void k_gemm(const float* __restrict__ X, const float* __restrict__ Wm,
                       const float* __restrict__ bias, float* __restrict__ Y) {
    constexpr int PG = 128 / TP;            // pix groups
    constexpr int NT = (BM / TM) * PG;      // threads
    __shared__ float sA[16][BM];
    __shared__ float sB[16][128];
    int tid = threadIdx.x;
    int tx = tid % PG;
    int ty = tid / PG;
    int pix0 = blockIdx.x * 128;
    int m0   = blockIdx.y * BM;
    int n    = blockIdx.z;
    int Mtot = gridDim.y * BM;
    const float* xb = X + (size_t)n*CC*HW + pix0;

    float acc[TM][TP];
#pragma unroll
    for (int i = 0; i < TM; i++)
#pragma unroll
        for (int j = 0; j < TP; j++) acc[i][j] = 0.f;

    for (int c0 = 0; c0 < 256; c0 += 16) {
        __syncthreads();
        for (int i = tid; i < BM*16; i += NT) {
            int ml = i >> 4, cl = i & 15;
            sA[cl][ml] = Wm[(m0+ml)*256 + c0 + cl];
        }
        for (int i = tid; i < 2048; i += NT) {
            int px = i & 127, cl = i >> 7;
            sB[cl][px] = xb[(size_t)(c0+cl)*HW + px];
        }
        __syncthreads();
#pragma unroll
        for (int cl = 0; cl < 16; cl++) {
            float a[TM], b[TP];
#pragma unroll
            for (int i = 0; i < TM; i += 4)
                *(float4*)(a+i) = *(const float4*)(&sA[cl][ty*TM + i]);
#pragma unroll
            for (int j = 0; j < TP; j += 4)
                *(float4*)(b+j) = *(const float4*)(&sB[cl][tx*TP + j]);
#pragma unroll
            for (int i = 0; i < TM; i++)
#pragma unroll
                for (int j = 0; j < TP; j++) acc[i][j] += a[i]*b[j];
        }
    }
#pragma unroll
    for (int i = 0; i < TM; i++) {
        int m = m0 + ty*TM + i;
        float bv = BIAS ? bias[m] : 0.f;
        float* yp = Y + ((size_t)n*Mtot + m)*HW + pix0 + tx*TP;
#pragma unroll
        for (int j = 0; j < TP; j += 4) {
            float4 v = make_float4(acc[i][j]+bv, acc[i][j+1]+bv, acc[i][j+2]+bv, acc[i][j+3]+bv);
            *(float4*)(yp + j) = v;
        }
    }
}

// ---------------------------------------------------------------------------
// Kernel 2: 3x3 encoder conv (100 out ch) + per-pixel softmax over K2=25.
// Block = (n, row-pair); threads (w=64, p=4). Each thread computes 2 output
// rows (h0, h0+1) for its sub-pixel p; softmax over k fully in registers.
// ---------------------------------------------------------------------------
__global__ void k_enc(const float* __restrict__ t, const float* __restrict__ We,
                      const float* __restrict__ be, float* __restrict__ kern) {
    __shared__ float st[8*4*68];        // [ml][r(4)][ww] rows h0-1..h0+2
    __shared__ float swt[8*9*4*28];     // [ml][tap][p][k(pad28)]
    int w = threadIdx.x;
    int p = threadIdx.y;
    int tid = p*64 + w;
    int n  = blockIdx.x >> 5;
    int h0 = (blockIdx.x & 31) * 2;
    const float* tb = t + (size_t)n*CM*HW;

    float acc[2][28];
#pragma unroll
    for (int k = 0; k < 28; k++) { acc[0][k] = 0.f; acc[1][k] = 0.f; }

    for (int m0 = 0; m0 < 64; m0 += 8) {
        __syncthreads();
        // stage t tile: rows h0-1..h0+2, channels m0..m0+7, cols -1..66 zero-padded
        for (int i = tid; i < 8*4*68; i += 256) {
            int ml = i / 272;
            int rem = i % 272;
            int r  = rem / 68;
            int ww = rem % 68;
            int hh = h0 + r - 1;
            int wx = ww - 1;
            float v = 0.f;
            if (hh >= 0 && hh < 64 && wx >= 0 && wx < 64)
                v = tb[(size_t)(m0+ml)*HW + hh*64 + wx];
            st[i] = v;
        }
        // stage weights transposed to k-contiguous
        for (int i = tid; i < 8*9*4*28; i += 256) {
            int k   = i % 28;
            int pp  = (i / 28) % 4;
            int tap = (i / 112) % 9;
            int ml  = i / 1008;
            float v = 0.f;
            if (k < 25) v = We[(k*4+pp)*576 + (m0+ml)*9 + tap];
            swt[i] = v;
        }
        __syncthreads();

        for (int ml = 0; ml < 8; ml++) {
#pragma unroll
            for (int tap = 0; tap < 9; tap++) {
                int di = tap / 3, dj = tap % 3;
                float tv0 = st[ml*272 + di*68     + (w + dj)];
                float tv1 = st[ml*272 + (di+1)*68 + (w + dj)];
                const float4* wp = (const float4*)(swt + ((ml*9 + tap)*4 + p)*28);
#pragma unroll
                for (int q = 0; q < 7; q++) {
                    float4 wv = wp[q];
                    acc[0][4*q+0] += tv0*wv.x; acc[0][4*q+1] += tv0*wv.y;
                    acc[0][4*q+2] += tv0*wv.z; acc[0][4*q+3] += tv0*wv.w;
                    acc[1][4*q+0] += tv1*wv.x; acc[1][4*q+1] += tv1*wv.y;
                    acc[1][4*q+2] += tv1*wv.z; acc[1][4*q+3] += tv1*wv.w;
                }
            }
        }
    }

    // softmax over k = 0..24 for both rows
#pragma unroll
    for (int r = 0; r < 2; r++) {
        float mx = -1e30f;
#pragma unroll
        for (int k = 0; k < 25; k++) {
            acc[r][k] += be[k*4 + p];
            mx = fmaxf(mx, acc[r][k]);
        }
        float s = 0.f;
#pragma unroll
        for (int k = 0; k < 25; k++) {
            acc[r][k] = __expf(acc[r][k] - mx);
            s += acc[r][k];
        }
        float inv = 1.f / s;
        float* kp = kern + ((size_t)(n*HW + (h0+r)*64 + w) * 25) * 4 + p;
#pragma unroll
        for (int k = 0; k < 25; k++) kp[k*4] = acc[r][k] * inv;
    }
}

// ---------------------------------------------------------------------------
// Kernel 4: reassembly of y = W_out*x directly into the final output.
// out[n,o,2h+i,2w+j] = sum_k y_pad[n,o,h+ki-2,w+kj-2]*kern[n,h,w,k,(i*2+j)] + bo[o]
// Block = (n,h); threads (w=64, cg=4). o chunked by 32; thread owns 8 o, 4 p.
// Dynamic smem: sk[25][64][4] + sy[32][5][68]  (69120 B)
// ---------------------------------------------------------------------------
__global__ void k_reasm_out(const float* __restrict__ y, const float* __restrict__ kern,
                            const float* __restrict__ bo, float* __restrict__ out) {
    extern __shared__ float smem[];
    float* sk = smem;              // [k][w][p]
    float* sy = smem + 25*64*4;    // [ol][r][ww]

    int w  = threadIdx.x;
    int cg = threadIdx.y;
    int tid = cg*64 + w;
    int n = blockIdx.x >> 6;
    int h = blockIdx.x & 63;

    const float* kb = kern + (size_t)(n*HW + h*64) * 100;
    for (int i = tid; i < 6400; i += 256) {
        int ww = i / 100;
        int r  = i % 100;
        int k  = r >> 2;
        int pp = r & 3;
        sk[k*256 + ww*4 + pp] = kb[ww*100 + r];
    }

    for (int c0 = 0; c0 < 256; c0 += 32) {
        __syncthreads();
        for (int i = tid; i < 32*5*68; i += 256) {
            int cl = i / 340;
            int r  = (i / 68) % 5;
            int ww = i % 68;
            int hh = h + r - 2;
            int wx = ww - 2;
            float v = 0.f;
            if (hh >= 0 && hh < 64 && wx >= 0 && wx < 64)
                v = y[((size_t)(n*CC + c0 + cl) * 64 + hh) * 64 + wx];
            sy[i] = v;
        }
        __syncthreads();

        float acc[8][4];
#pragma unroll
        for (int cc = 0; cc < 8; cc++)
#pragma unroll
            for (int q = 0; q < 4; q++) acc[cc][q] = 0.f;

        int cl0 = cg * 8;
#pragma unroll
        for (int k = 0; k < 25; k++) {
            int ki = k / 5, kj = k % 5;
            float4 kv = *(const float4*)(sk + k*256 + w*4);
#pragma unroll
            for (int cc = 0; cc < 8; cc++) {
                float yv = sy[(cl0+cc)*340 + ki*68 + (w + kj)];
                acc[cc][0] += yv*kv.x; acc[cc][1] += yv*kv.y;
                acc[cc][2] += yv*kv.z; acc[cc][3] += yv*kv.w;
            }
        }

#pragma unroll
        for (int cc = 0; cc < 8; cc++) {
            int c = c0 + cl0 + cc;
            float b = bo[c];
            float* op = out + ((size_t)(n*CC + c) * 128 + 2*h) * 128 + 2*w;
            *(float2*)(op)       = make_float2(acc[cc][0]+b, acc[cc][1]+b);
            *(float2*)(op + 128) = make_float2(acc[cc][2]+b, acc[cc][3]+b);
        }
    }
}

// ---------------------------------------------------------------------------
extern "C" void kernel_launch(void* const* d_in, const int* in_sizes, int n_in,
                              void* d_out, int out_size) {
    const float* x   = (const float*)d_in[0];
    const float* Wd  = (const float*)d_in[1];
    const float* bd  = (const float*)d_in[2];
    const float* We  = (const float*)d_in[3];
    const float* be  = (const float*)d_in[4];
    const float* Wo  = (const float*)d_in[5];
    const float* bo  = (const float*)d_in[6];
    float* out = (float*)d_out;

    float *t, *kern, *y;
    cudaGetSymbolAddress((void**)&t,    g_t);
    cudaGetSymbolAddress((void**)&kern, g_kern);
    cudaGetSymbolAddress((void**)&y,    g_y);

    cudaFuncSetAttribute(k_reasm_out, cudaFuncAttributeMaxDynamicSharedMemorySize, 69120);

    // t = Wd*x + bd   (64 x 256 x 16384)
    k_gemm<64,4,8,true><<<dim3(32,1,NN), 256>>>(x, Wd, bd, t);
    // kern = softmax(conv3x3(t))
    k_enc<<<NN*32, dim3(64,4)>>>(t, We, be, kern);
    // y = Wo*x        (256 x 256 x 16384) -- low-res, 4x fewer FLOPs than after upsample
    k_gemm<128,8,8,false><<<dim3(32,2,NN), 256>>>(x, Wo, nullptr, y);
    // out = reasm(y, kern) + bo
    k_reasm_out<<<NN*HH, dim3(64,4), 69120>>>(y, kern, bo, out);
}

// round 6
// speedup vs baseline: 2.1192x; 1.1145x over previous
#include <cuda_runtime.h>
#include <cuda_bf16.h>

#define NN 4
#define CC 256
#define HH 64
#define WW 64
#define CM 64
#define K2 25
#define HW (HH*WW)          // 4096
#define GTOT (NN*HW)        // 16384 total low-res pixels

// Scratch (device globals; allocation-free per harness rules)
__device__ float g_t[NN*CM*HW];     // 4 MB : down-projected features [n][m][hw]
__device__ float g_e[100*GTOT];     // 26 MB: raw encoder conv output [o][g]
__device__ float g_y[NN*CC*HW];     // 16 MB: y = W_out * x (low-res)  [n][c][hw]

// ---------------------------------------------------------------------------
// Tiled fp32 GEMM over pixels with register double-buffering:
//   Y[n,m,pix] = sum_c Wm[m,c]*X[n,c,pix] (+b[m])
// Block tile BM x 128pix, K-step 16, thread tile TM x TP, NT threads.
// ---------------------------------------------------------------------------
template<int BM, int TM, int TP, bool BIAS>
__global__ void k_gemm(const float* __restrict__ X, const float* __restrict__ Wm,
                       const float* __restrict__ bias, float* __restrict__ Y) {
    constexpr int PG = 128 / TP;
    constexpr int NT = (BM / TM) * PG;
    constexpr int NA = BM*16 / NT;
    constexpr int NB = 2048 / NT;
    __shared__ float sA[16][BM];
    __shared__ float sB[16][128];
    int tid = threadIdx.x;
    int tx = tid % PG;
    int ty = tid / PG;
    int pix0 = blockIdx.x * 128;
    int m0   = blockIdx.y * BM;
    int n    = blockIdx.z;
    int Mtot = gridDim.y * BM;
    const float* xb = X + (size_t)n*CC*HW + pix0;

    float acc[TM][TP];
#pragma unroll
    for (int i = 0; i < TM; i++)
#pragma unroll
        for (int j = 0; j < TP; j++) acc[i][j] = 0.f;

    float pa[NA], pb[NB];
    // initial prefetch (c0 = 0)
#pragma unroll
    for (int i = 0; i < NA; i++) {
        int idx = i*NT + tid;
        pa[i] = Wm[(m0 + (idx>>4))*256 + (idx & 15)];
    }
#pragma unroll
    for (int i = 0; i < NB; i++) {
        int idx = i*NT + tid;
        pb[i] = xb[(size_t)(idx>>7)*HW + (idx & 127)];
    }

    for (int c0 = 0; c0 < 256; c0 += 16) {
#pragma unroll
        for (int i = 0; i < NA; i++) {
            int idx = i*NT + tid;
            sA[idx & 15][idx >> 4] = pa[i];
        }
#pragma unroll
        for (int i = 0; i < NB; i++) {
            int idx = i*NT + tid;
            sB[idx >> 7][idx & 127] = pb[i];
        }
        __syncthreads();
        if (c0 + 16 < 256) {
#pragma unroll
            for (int i = 0; i < NA; i++) {
                int idx = i*NT + tid;
                pa[i] = Wm[(m0 + (idx>>4))*256 + c0 + 16 + (idx & 15)];
            }
#pragma unroll
            for (int i = 0; i < NB; i++) {
                int idx = i*NT + tid;
                pb[i] = xb[(size_t)(c0 + 16 + (idx>>7))*HW + (idx & 127)];
            }
        }
#pragma unroll
        for (int cl = 0; cl < 16; cl++) {
            float a[TM], b[TP];
#pragma unroll
            for (int i = 0; i < TM; i += 4)
                *(float4*)(a+i) = *(const float4*)(&sA[cl][ty*TM + i]);
#pragma unroll
            for (int j = 0; j < TP; j += 4)
                *(float4*)(b+j) = *(const float4*)(&sB[cl][tx*TP + j]);
#pragma unroll
            for (int i = 0; i < TM; i++)
#pragma unroll
                for (int j = 0; j < TP; j++) acc[i][j] += a[i]*b[j];
        }
        __syncthreads();
    }
#pragma unroll
    for (int i = 0; i < TM; i++) {
        int m = m0 + ty*TM + i;
        float bv = BIAS ? bias[m] : 0.f;
        float* yp = Y + ((size_t)n*Mtot + m)*HW + pix0 + tx*TP;
#pragma unroll
        for (int j = 0; j < TP; j += 4) {
            float4 v = make_float4(acc[i][j]+bv, acc[i][j+1]+bv, acc[i][j+2]+bv, acc[i][j+3]+bv);
            *(float4*)(yp + j) = v;
        }
    }
}

// ---------------------------------------------------------------------------
// Encoder 3x3 conv as a GEMM:  e[o, g] = sum_{m,tap} We[o,m,tap] * tshift(m,g,tap)
// Block: 64 o's x 128 g's (2 rows of 64 within one n). 128 threads, 8x8 tiles.
// K loop: 4 chunks of 16 m, inner 16 m x 9 taps. Raw output (no bias/softmax).
// Dynamic smem: sA[16][9][64] (9216) + sB[16][4][68] (4352) = 54272 B.
// ---------------------------------------------------------------------------
__global__ void k_enc_gemm(const float* __restrict__ t, const float* __restrict__ We,
                           float* __restrict__ e) {
    extern __shared__ float smem[];
    float* sA = smem;           // [(ml*9+tap)*64 + o]
    float* sB = smem + 9216;    // [ml*272 + r*68 + ww]
    int tid = threadIdx.x;      // 128
    int tx = tid & 15;
    int ty = tid >> 4;
    int g0 = blockIdx.x * 128;
    int o0 = blockIdx.y * 64;
    int n  = g0 >> 12;
    int h0 = (g0 & 4095) >> 6;  // even; rows h0, h0+1
    const float* tb = t + (size_t)n*CM*HW;

    float acc[8][8];
#pragma unroll
    for (int i = 0; i < 8; i++)
#pragma unroll
        for (int j = 0; j < 8; j++) acc[i][j] = 0.f;

    int rb = tx >> 3;           // output row within tile (0/1)
    int wb = (tx & 7) * 8;      // col base

    for (int m0 = 0; m0 < 64; m0 += 16) {
        __syncthreads();
        for (int i = tid; i < 4352; i += 128) {
            int ml = i / 272;
            int rem = i % 272;
            int r = rem / 68, ww = rem % 68;
            int hh = h0 + r - 1, wx = ww - 1;
            float v = 0.f;
            if (hh >= 0 && hh < 64 && wx >= 0 && wx < 64)
                v = tb[(size_t)(m0+ml)*HW + hh*64 + wx];
            sB[i] = v;
        }
        for (int i = tid; i < 9216; i += 128) {
            int o = i & 63;
            int tap = (i >> 6) % 9;
            int ml = i / 576;
            int og = o0 + o;
            sA[i] = (og < 100) ? We[og*576 + (m0+ml)*9 + tap] : 0.f;
        }
        __syncthreads();

        for (int ml = 0; ml < 16; ml++) {
#pragma unroll
            for (int tap = 0; tap < 9; tap++) {
                const int di = tap / 3, dj = tap % 3;
                const float* ap = sA + (ml*9 + tap)*64 + ty*8;
                float a[8];
                *(float4*)(a)   = *(const float4*)(ap);
                *(float4*)(a+4) = *(const float4*)(ap+4);
                const float* bp = sB + ml*272 + (rb + di)*68 + wb + dj;
                float b[8];
#pragma unroll
                for (int j = 0; j < 8; j++) b[j] = bp[j];
#pragma unroll
                for (int i = 0; i < 8; i++)
#pragma unroll
                    for (int j = 0; j < 8; j++) acc[i][j] += a[i]*b[j];
            }
        }
    }

#pragma unroll
    for (int oo = 0; oo < 8; oo++) {
        int o = o0 + ty*8 + oo;
        if (o < 100) {
            float* ep = e + (size_t)o*GTOT + g0 + tx*8;
            *(float4*)(ep)   = make_float4(acc[oo][0], acc[oo][1], acc[oo][2], acc[oo][3]);
            *(float4*)(ep+4) = make_float4(acc[oo][4], acc[oo][5], acc[oo][6], acc[oo][7]);
        }
    }
}

// ---------------------------------------------------------------------------
// Reassembly with fused softmax, writing the final output.
// Block = (n,h) x csplit(2). Threads (w=64, p=4).
// Stage 1 (once): thread (w,p) softmaxes e[*, g] over 25 k (bias added) -> sk[k][w][p].
// Stage 2 (4 chunks of 32 ch): sy[g8][r5][ww68][4] ; per k: 3x LDS.128 + 32 FFMA.
// Dynamic smem: sk 6400 + sy 10880 floats = 69120 B.
// ---------------------------------------------------------------------------
__global__ void k_reasm_out(const float* __restrict__ y, const float* __restrict__ e,
                            const float* __restrict__ be, const float* __restrict__ bo,
                            float* __restrict__ out) {
    extern __shared__ float smem[];
    float* sk = smem;              // [k][w][p] : k*256 + w*4 + p
    float* sy = smem + 6400;       // [g][r][ww][4] : g*1360 + r*272 + ww*4 + c4

    int w  = threadIdx.x;
    int cg = threadIdx.y;          // = p for the softmax stage
    int tid = cg*64 + w;
    int n = blockIdx.x >> 6;
    int h = blockIdx.x & 63;
    int cbase = blockIdx.y * 128;

    // ---- fused softmax over k for pixel (n,h,w), sub-pixel p=cg ----
    {
        int g = n*HW + h*64 + w;
        float ek[25];
        float mx = -1e30f;
#pragma unroll
        for (int k = 0; k < 25; k++) {
            ek[k] = e[(size_t)(k*4 + cg)*GTOT + g] + be[k*4 + cg];
            mx = fmaxf(mx, ek[k]);
        }
        float s = 0.f;
#pragma unroll
        for (int k = 0; k < 25; k++) {
            ek[k] = __expf(ek[k] - mx);
            s += ek[k];
        }
        float inv = 1.f / s;
#pragma unroll
        for (int k = 0; k < 25; k++) sk[k*256 + w*4 + cg] = ek[k] * inv;
    }

    for (int c0 = cbase; c0 < cbase + 128; c0 += 32) {
        __syncthreads();   // also guards sk visibility on first iteration
        for (int i = tid; i < 10880; i += 256) {
            int cl = i / 340;
            int rem = i % 340;
            int r = rem / 68, ww = rem % 68;
            int hh = h + r - 2, wx = ww - 2;
            float v = 0.f;
            if (hh >= 0 && hh < 64 && wx >= 0 && wx < 64)
                v = y[((size_t)(n*CC + c0 + cl) * 64 + hh) * 64 + wx];
            sy[((cl>>2)*5 + r)*272 + ww*4 + (cl & 3)] = v;
        }
        __syncthreads();

        float4 acc[8];
#pragma unroll
        for (int cc = 0; cc < 8; cc++) acc[cc] = make_float4(0.f, 0.f, 0.f, 0.f);

        const float* skp = sk + w*4;
        const float* syp = sy + (cg*2)*1360 + w*4;
#pragma unroll
        for (int k = 0; k < 25; k++) {
            const int ki = k / 5, kj = k % 5;
            float4 kv = *(const float4*)(skp + k*256);
            float4 y0 = *(const float4*)(syp + ki*272 + kj*4);
            float4 y1 = *(const float4*)(syp + 1360 + ki*272 + kj*4);
            acc[0].x += y0.x*kv.x; acc[0].y += y0.x*kv.y; acc[0].z += y0.x*kv.z; acc[0].w += y0.x*kv.w;
            acc[1].x += y0.y*kv.x; acc[1].y += y0.y*kv.y; acc[1].z += y0.y*kv.z; acc[1].w += y0.y*kv.w;
            acc[2].x += y0.z*kv.x; acc[2].y += y0.z*kv.y; acc[2].z += y0.z*kv.z; acc[2].w += y0.z*kv.w;
            acc[3].x += y0.w*kv.x; acc[3].y += y0.w*kv.y; acc[3].z += y0.w*kv.z; acc[3].w += y0.w*kv.w;
            acc[4].x += y1.x*kv.x; acc[4].y += y1.x*kv.y; acc[4].z += y1.x*kv.z; acc[4].w += y1.x*kv.w;
            acc[5].x += y1.y*kv.x; acc[5].y += y1.y*kv.y; acc[5].z += y1.y*kv.z; acc[5].w += y1.y*kv.w;
            acc[6].x += y1.z*kv.x; acc[6].y += y1.z*kv.y; acc[6].z += y1.z*kv.z; acc[6].w += y1.z*kv.w;
            acc[7].x += y1.w*kv.x; acc[7].y += y1.w*kv.y; acc[7].z += y1.w*kv.z; acc[7].w += y1.w*kv.w;
        }

#pragma unroll
        for (int cc = 0; cc < 8; cc++) {
            int c = c0 + cg*8 + cc;
            float b = bo[c];
            float* op = out + ((size_t)(n*CC + c) * 128 + 2*h) * 128 + 2*w;
            *(float2*)(op)       = make_float2(acc[cc].x + b, acc[cc].y + b);
            *(float2*)(op + 128) = make_float2(acc[cc].z + b, acc[cc].w + b);
        }
    }
}

// ---------------------------------------------------------------------------
extern "C" void kernel_launch(void* const* d_in, const int* in_sizes, int n_in,
                              void* d_out, int out_size) {
    const float* x   = (const float*)d_in[0];
    const float* Wd  = (const float*)d_in[1];
    const float* bd  = (const float*)d_in[2];
    const float* We  = (const float*)d_in[3];
    const float* be  = (const float*)d_in[4];
    const float* Wo  = (const float*)d_in[5];
    const float* bo  = (const float*)d_in[6];
    float* out = (float*)d_out;

    float *t, *e, *y;
    cudaGetSymbolAddress((void**)&t, g_t);
    cudaGetSymbolAddress((void**)&e, g_e);
    cudaGetSymbolAddress((void**)&y, g_y);

    cudaFuncSetAttribute(k_enc_gemm,  cudaFuncAttributeMaxDynamicSharedMemorySize, 54272);
    cudaFuncSetAttribute(k_reasm_out, cudaFuncAttributeMaxDynamicSharedMemorySize, 69120);

    // t = Wd*x + bd   (64 x 256 x 16384)
    k_gemm<64,4,8,true><<<dim3(32,1,NN), 256>>>(x, Wd, bd, t);
    // e = conv3x3(t)  (raw, softmax fused into reassembly)
    k_enc_gemm<<<dim3(128,2), 128, 54272>>>(t, We, e);
    // y = Wo*x        (256 x 256 x 16384)
    k_gemm<128,8,8,false><<<dim3(32,2,NN), 256>>>(x, Wo, nullptr, y);
    // out = reasm(y, softmax(e+be)) + bo
    k_reasm_out<<<dim3(256,2), dim3(64,4), 69120>>>(y, e, be, bo, out);
}

// round 7
// speedup vs baseline: 2.2817x; 1.0767x over previous
#include <cuda_runtime.h>
#include <cuda_bf16.h>

#define NN 4
#define CC 256
#define HH 64
#define WW 64
#define CM 64
#define K2 25
#define HW (HH*WW)          // 4096
#define GTOT (NN*HW)        // 16384 total low-res pixels

// Scratch (device globals; allocation-free per harness rules)
__device__ float g_t[NN*CM*HW];     // 4 MB : down-projected features [n][m][hw]
__device__ float g_e[100*GTOT];     // 26 MB: raw encoder conv output [o][g]
__device__ float g_y[NN*CC*HW];     // 16 MB: y = W_out * x (low-res)  [n][c][hw]

// ---------------------------------------------------------------------------
// Tiled fp32 GEMM over pixels with register double-buffering:
//   Y[n,m,pix] = sum_c Wm[m,c]*X[n,c,pix] (+b[m])
// ---------------------------------------------------------------------------
template<int BM, int TM, int TP, bool BIAS>
__global__ void k_gemm(const float* __restrict__ X, const float* __restrict__ Wm,
                       const float* __restrict__ bias, float* __restrict__ Y) {
    constexpr int PG = 128 / TP;
    constexpr int NT = (BM / TM) * PG;
    constexpr int NA = BM*16 / NT;
    constexpr int NB = 2048 / NT;
    __shared__ float sA[16][BM];
    __shared__ float sB[16][128];
    int tid = threadIdx.x;
    int tx = tid % PG;
    int ty = tid / PG;
    int pix0 = blockIdx.x * 128;
    int m0   = blockIdx.y * BM;
    int n    = blockIdx.z;
    int Mtot = gridDim.y * BM;
    const float* xb = X + (size_t)n*CC*HW + pix0;

    float acc[TM][TP];
#pragma unroll
    for (int i = 0; i < TM; i++)
#pragma unroll
        for (int j = 0; j < TP; j++) acc[i][j] = 0.f;

    float pa[NA], pb[NB];
#pragma unroll
    for (int i = 0; i < NA; i++) {
        int idx = i*NT + tid;
        pa[i] = Wm[(m0 + (idx>>4))*256 + (idx & 15)];
    }
#pragma unroll
    for (int i = 0; i < NB; i++) {
        int idx = i*NT + tid;
        pb[i] = xb[(size_t)(idx>>7)*HW + (idx & 127)];
    }

    for (int c0 = 0; c0 < 256; c0 += 16) {
#pragma unroll
        for (int i = 0; i < NA; i++) {
            int idx = i*NT + tid;
            sA[idx & 15][idx >> 4] = pa[i];
        }
#pragma unroll
        for (int i = 0; i < NB; i++) {
            int idx = i*NT + tid;
            sB[idx >> 7][idx & 127] = pb[i];
        }
        __syncthreads();
        if (c0 + 16 < 256) {
#pragma unroll
            for (int i = 0; i < NA; i++) {
                int idx = i*NT + tid;
                pa[i] = Wm[(m0 + (idx>>4))*256 + c0 + 16 + (idx & 15)];
            }
#pragma unroll
            for (int i = 0; i < NB; i++) {
                int idx = i*NT + tid;
                pb[i] = xb[(size_t)(c0 + 16 + (idx>>7))*HW + (idx & 127)];
            }
        }
#pragma unroll
        for (int cl = 0; cl < 16; cl++) {
            float a[TM], b[TP];
#pragma unroll
            for (int i = 0; i < TM; i += 4)
                *(float4*)(a+i) = *(const float4*)(&sA[cl][ty*TM + i]);
#pragma unroll
            for (int j = 0; j < TP; j += 4)
                *(float4*)(b+j) = *(const float4*)(&sB[cl][tx*TP + j]);
#pragma unroll
            for (int i = 0; i < TM; i++)
#pragma unroll
                for (int j = 0; j < TP; j++) acc[i][j] += a[i]*b[j];
        }
        __syncthreads();
    }
#pragma unroll
    for (int i = 0; i < TM; i++) {
        int m = m0 + ty*TM + i;
        float bv = BIAS ? bias[m] : 0.f;
        float* yp = Y + ((size_t)n*Mtot + m)*HW + pix0 + tx*TP;
#pragma unroll
        for (int j = 0; j < TP; j += 4) {
            float4 v = make_float4(acc[i][j]+bv, acc[i][j+1]+bv, acc[i][j+2]+bv, acc[i][j+3]+bv);
            *(float4*)(yp + j) = v;
        }
    }
}

// ---------------------------------------------------------------------------
// Encoder 3x3 conv as a GEMM:  e[o, g] = sum_{m,tap} We[o,m,tap] * tshift(m,g,tap)
// Block: 64 o's x 128 g's. 128 threads, 8x8 tiles. Structured staging (no div).
// ---------------------------------------------------------------------------
__global__ void k_enc_gemm(const float* __restrict__ t, const float* __restrict__ We,
                           float* __restrict__ e) {
    extern __shared__ float smem[];
    float* sA = smem;           // [(ml*9+tap)*64 + o]
    float* sB = smem + 9216;    // [ml*272 + r*68 + ww]
    int tid = threadIdx.x;      // 128
    int tx = tid & 15;
    int ty = tid >> 4;
    int g0 = blockIdx.x * 128;
    int o0 = blockIdx.y * 64;
    int n  = g0 >> 12;
    int h0 = (g0 & 4095) >> 6;  // even; rows h0, h0+1
    const float* tb = t + (size_t)n*CM*HW;

    // staging roles (no divisions)
    int s_ml = tid >> 3;        // 0..15  (channel for sB)
    int s_s  = tid & 7;         // 0..7   (lane slot for sB)
    int s_o  = tid & 63;        // 0..63  (o for sA)
    int s_hf = tid >> 6;        // 0..1   (tap parity for sA)
    int og_a = o0 + s_o;
    bool ook = (og_a < 100);

    float acc[8][8];
#pragma unroll
    for (int i = 0; i < 8; i++)
#pragma unroll
        for (int j = 0; j < 8; j++) acc[i][j] = 0.f;

    int rb = tx >> 3;
    int wb = (tx & 7) * 8;

    for (int m0 = 0; m0 < 64; m0 += 16) {
        __syncthreads();
        // sB: channel s_ml, rows h0-1..h0+2, cols -1..66 (structured)
        {
            const float* tc = tb + (size_t)(m0 + s_ml)*HW;
            float* sBc = sB + s_ml*272;
#pragma unroll
            for (int r = 0; r < 4; r++) {
                int hh = h0 + r - 1;
                bool hok = ((unsigned)hh < 64u);
                const float* tr = tc + hh*64;
                float* sr = sBc + r*68;
#pragma unroll
                for (int j = 0; j < 9; j++) {
                    int ww = s_s + 8*j;
                    if (ww < 68) {
                        int wx = ww - 1;
                        sr[ww] = (hok && (unsigned)wx < 64u) ? tr[wx] : 0.f;
                    }
                }
            }
        }
        // sA: o = s_o, taps of parity s_hf, all 16 ml (structured)
        {
            const float* wrow = ook ? (We + (size_t)og_a*576 + m0*9) : nullptr;
#pragma unroll
            for (int ml = 0; ml < 16; ml++) {
                float* sa = sA + ml*576 + s_o;   // (ml*9+tap)*64+o = ml*576 + tap*64 + o
#pragma unroll
                for (int tap = 0; tap < 9; tap++) {
                    if ((tap & 1) == s_hf)
                        sa[tap*64] = ook ? wrow[ml*9 + tap] : 0.f;
                }
            }
        }
        __syncthreads();

        for (int ml = 0; ml < 16; ml++) {
#pragma unroll
            for (int tap = 0; tap < 9; tap++) {
                const int di = tap / 3, dj = tap % 3;
                const float* ap = sA + (ml*9 + tap)*64 + ty*8;
                float a[8];
                *(float4*)(a)   = *(const float4*)(ap);
                *(float4*)(a+4) = *(const float4*)(ap+4);
                const float* bp = sB + ml*272 + (rb + di)*68 + wb + dj;
                float b[8];
#pragma unroll
                for (int j = 0; j < 8; j++) b[j] = bp[j];
#pragma unroll
                for (int i = 0; i < 8; i++)
#pragma unroll
                    for (int j = 0; j < 8; j++) acc[i][j] += a[i]*b[j];
            }
        }
    }

#pragma unroll
    for (int oo = 0; oo < 8; oo++) {
        int o = o0 + ty*8 + oo;
        if (o < 100) {
            float* ep = e + (size_t)o*GTOT + g0 + tx*8;
            *(float4*)(ep)   = make_float4(acc[oo][0], acc[oo][1], acc[oo][2], acc[oo][3]);
            *(float4*)(ep+4) = make_float4(acc[oo][4], acc[oo][5], acc[oo][6], acc[oo][7]);
        }
    }
}

// ---------------------------------------------------------------------------
// Reassembly with fused softmax, writing the final output.
// Block = (n,h) x csplit(2). Threads (w=64, p=4). Structured sy staging (no div).
// ---------------------------------------------------------------------------
__global__ void k_reasm_out(const float* __restrict__ y, const float* __restrict__ e,
                            const float* __restrict__ be, const float* __restrict__ bo,
                            float* __restrict__ out) {
    extern __shared__ float smem[];
    float* sk = smem;              // [k][w][p] : k*256 + w*4 + p
    float* sy = smem + 6400;       // [g][r][ww][4] : g*1360 + r*272 + ww*4 + c4

    int w  = threadIdx.x;
    int cg = threadIdx.y;          // = p for the softmax stage
    int tid = cg*64 + w;
    int n = blockIdx.x >> 6;
    int h = blockIdx.x & 63;
    int cbase = blockIdx.y * 128;

    // staging roles (no divisions)
    int cl = tid >> 3;             // 0..31 channel within chunk
    int s  = tid & 7;              // 0..7  lane slot
    float* syc = sy + (cl >> 2)*5*272 + (cl & 3);

    // ---- fused softmax over k for pixel (n,h,w), sub-pixel p=cg ----
    {
        int g = n*HW + h*64 + w;
        float ek[25];
        float mx = -1e30f;
#pragma unroll
        for (int k = 0; k < 25; k++) {
            ek[k] = e[(size_t)(k*4 + cg)*GTOT + g] + be[k*4 + cg];
            mx = fmaxf(mx, ek[k]);
        }
        float s0 = 0.f;
#pragma unroll
        for (int k = 0; k < 25; k++) {
            ek[k] = __expf(ek[k] - mx);
            s0 += ek[k];
        }
        float inv = 1.f / s0;
#pragma unroll
        for (int k = 0; k < 25; k++) sk[k*256 + w*4 + cg] = ek[k] * inv;
    }

    for (int c0 = cbase; c0 < cbase + 128; c0 += 32) {
        __syncthreads();   // also guards sk visibility on first iteration
        // stage y tile: channel c0+cl, rows h-2..h+2, cols -2..65 (structured)
        {
            const float* ybase = y + (size_t)(n*CC + c0 + cl)*HW;
#pragma unroll
            for (int r = 0; r < 5; r++) {
                int hh = h + r - 2;
                bool hok = ((unsigned)hh < 64u);
                const float* yr = ybase + hh*64;
                float* syr = syc + r*272;
#pragma unroll
                for (int j = 0; j < 9; j++) {
                    int ww = s + 8*j;
                    if (ww < 68) {
                        int wx = ww - 2;
                        syr[ww*4] = (hok && (unsigned)wx < 64u) ? yr[wx] : 0.f;
                    }
                }
            }
        }
        __syncthreads();

        float4 acc[8];
#pragma unroll
        for (int cc = 0; cc < 8; cc++) acc[cc] = make_float4(0.f, 0.f, 0.f, 0.f);

        const float* skp = sk + w*4;
        const float* syp = sy + (cg*2)*1360 + w*4;
#pragma unroll
        for (int k = 0; k < 25; k++) {
            const int ki = k / 5, kj = k % 5;
            float4 kv = *(const float4*)(skp + k*256);
            float4 y0 = *(const float4*)(syp + ki*272 + kj*4);
            float4 y1 = *(const float4*)(syp + 1360 + ki*272 + kj*4);
            acc[0].x += y0.x*kv.x; acc[0].y += y0.x*kv.y; acc[0].z += y0.x*kv.z; acc[0].w += y0.x*kv.w;
            acc[1].x += y0.y*kv.x; acc[1].y += y0.y*kv.y; acc[1].z += y0.y*kv.z; acc[1].w += y0.y*kv.w;
            acc[2].x += y0.z*kv.x; acc[2].y += y0.z*kv.y; acc[2].z += y0.z*kv.z; acc[2].w += y0.z*kv.w;
            acc[3].x += y0.w*kv.x; acc[3].y += y0.w*kv.y; acc[3].z += y0.w*kv.z; acc[3].w += y0.w*kv.w;
            acc[4].x += y1.x*kv.x; acc[4].y += y1.x*kv.y; acc[4].z += y1.x*kv.z; acc[4].w += y1.x*kv.w;
            acc[5].x += y1.y*kv.x; acc[5].y += y1.y*kv.y; acc[5].z += y1.y*kv.z; acc[5].w += y1.y*kv.w;
            acc[6].x += y1.z*kv.x; acc[6].y += y1.z*kv.y; acc[6].z += y1.z*kv.z; acc[6].w += y1.z*kv.w;
            acc[7].x += y1.w*kv.x; acc[7].y += y1.w*kv.y; acc[7].z += y1.w*kv.z; acc[7].w += y1.w*kv.w;
        }

#pragma unroll
        for (int cc = 0; cc < 8; cc++) {
            int c = c0 + cg*8 + cc;
            float b = bo[c];
            float* op = out + ((size_t)(n*CC + c) * 128 + 2*h) * 128 + 2*w;
            *(float2*)(op)       = make_float2(acc[cc].x + b, acc[cc].y + b);
            *(float2*)(op + 128) = make_float2(acc[cc].z + b, acc[cc].w + b);
        }
    }
}

// ---------------------------------------------------------------------------
extern "C" void kernel_launch(void* const* d_in, const int* in_sizes, int n_in,
                              void* d_out, int out_size) {
    const float* x   = (const float*)d_in[0];
    const float* Wd  = (const float*)d_in[1];
    const float* bd  = (const float*)d_in[2];
    const float* We  = (const float*)d_in[3];
    const float* be  = (const float*)d_in[4];
    const float* Wo  = (const float*)d_in[5];
    const float* bo  = (const float*)d_in[6];
    float* out = (float*)d_out;

    float *t, *e, *y;
    cudaGetSymbolAddress((void**)&t, g_t);
    cudaGetSymbolAddress((void**)&e, g_e);
    cudaGetSymbolAddress((void**)&y, g_y);

    cudaFuncSetAttribute(k_enc_gemm,  cudaFuncAttributeMaxDynamicSharedMemorySize, 54272);
    cudaFuncSetAttribute(k_reasm_out, cudaFuncAttributeMaxDynamicSharedMemorySize, 69120);

    // t = Wd*x + bd   (64 x 256 x 16384)
    k_gemm<64,4,8,true><<<dim3(32,1,NN), 256>>>(x, Wd, bd, t);
    // e = conv3x3(t)  (raw, softmax fused into reassembly)
    k_enc_gemm<<<dim3(128,2), 128, 54272>>>(t, We, e);
    // y = Wo*x        (256 x 256 x 16384)
    k_gemm<128,8,8,false><<<dim3(32,2,NN), 256>>>(x, Wo, nullptr, y);
    // out = reasm(y, softmax(e+be)) + bo
    k_reasm_out<<<dim3(256,2), dim3(64,4), 69120>>>(y, e, be, bo, out);
}

// round 8
// speedup vs baseline: 2.4070x; 1.0549x over previous
#include <cuda_runtime.h>
#include <cuda_bf16.h>

#define NN 4
#define CC 256
#define HH 64
#define WW 64
#define CM 64
#define K2 25
#define HW (HH*WW)          // 4096
#define GTOT (NN*HW)        // 16384 total low-res pixels

typedef unsigned long long u64;

// ---- packed fp32x2 helpers (FFMA2: 2 fp32 FMAs per instruction) ----
__device__ __forceinline__ u64 pk2b(float v) {
    u64 r; asm("mov.b64 %0, {%1, %1};" : "=l"(r) : "f"(v)); return r;
}
__device__ __forceinline__ u64 pk2(float lo, float hi) {
    u64 r; asm("mov.b64 %0, {%1, %2};" : "=l"(r) : "f"(lo), "f"(hi)); return r;
}
__device__ __forceinline__ void fma2(u64 &d, u64 a, u64 b) {
    asm("fma.rn.f32x2 %0, %1, %2, %0;" : "+l"(d) : "l"(a), "l"(b));
}
__device__ __forceinline__ u64 add2(u64 a, u64 b) {
    u64 r; asm("add.rn.f32x2 %0, %1, %2;" : "=l"(r) : "l"(a), "l"(b)); return r;
}

// Scratch (device globals; allocation-free per harness rules)
__device__ float g_t[NN*CM*HW];     // 4 MB : down-projected features [n][m][hw]
__device__ float g_e[100*GTOT];     // 26 MB: raw encoder conv output [o][g]
__device__ float g_y[NN*CC*HW];     // 16 MB: y = W_out * x (low-res)  [n][c][hw]

// ---------------------------------------------------------------------------
// Tiled fp32 GEMM over pixels, register double-buffered, FFMA2 inner loop:
//   Y[n,m,pix] = sum_c Wm[m,c]*X[n,c,pix] (+b[m])
// ---------------------------------------------------------------------------
template<int BM, int TM, int TP, bool BIAS>
__global__ void k_gemm(const float* __restrict__ X, const float* __restrict__ Wm,
                       const float* __restrict__ bias, float* __restrict__ Y) {
    constexpr int PG = 128 / TP;
    constexpr int NT = (BM / TM) * PG;
    constexpr int NA = BM*16 / NT;
    constexpr int NB = 2048 / NT;
    __shared__ float sA[16][BM];
    __shared__ float sB[16][128];
    int tid = threadIdx.x;
    int tx = tid % PG;
    int ty = tid / PG;
    int pix0 = blockIdx.x * 128;
    int m0   = blockIdx.y * BM;
    int n    = blockIdx.z;
    int Mtot = gridDim.y * BM;
    const float* xb = X + (size_t)n*CC*HW + pix0;

    u64 acc[TM][TP/2];
#pragma unroll
    for (int i = 0; i < TM; i++)
#pragma unroll
        for (int j = 0; j < TP/2; j++) acc[i][j] = 0ull;

    float pa[NA], pb[NB];
#pragma unroll
    for (int i = 0; i < NA; i++) {
        int idx = i*NT + tid;
        pa[i] = Wm[(m0 + (idx>>4))*256 + (idx & 15)];
    }
#pragma unroll
    for (int i = 0; i < NB; i++) {
        int idx = i*NT + tid;
        pb[i] = xb[(size_t)(idx>>7)*HW + (idx & 127)];
    }

    for (int c0 = 0; c0 < 256; c0 += 16) {
#pragma unroll
        for (int i = 0; i < NA; i++) {
            int idx = i*NT + tid;
            sA[idx & 15][idx >> 4] = pa[i];
        }
#pragma unroll
        for (int i = 0; i < NB; i++) {
            int idx = i*NT + tid;
            sB[idx >> 7][idx & 127] = pb[i];
        }
        __syncthreads();
        if (c0 + 16 < 256) {
#pragma unroll
            for (int i = 0; i < NA; i++) {
                int idx = i*NT + tid;
                pa[i] = Wm[(m0 + (idx>>4))*256 + c0 + 16 + (idx & 15)];
            }
#pragma unroll
            for (int i = 0; i < NB; i++) {
                int idx = i*NT + tid;
                pb[i] = xb[(size_t)(c0 + 16 + (idx>>7))*HW + (idx & 127)];
            }
        }
#pragma unroll
        for (int cl = 0; cl < 16; cl++) {
            float a[TM];
            u64 bb[TP/2];
#pragma unroll
            for (int i = 0; i < TM; i += 4)
                *(float4*)(a+i) = *(const float4*)(&sA[cl][ty*TM + i]);
#pragma unroll
            for (int j = 0; j < TP; j += 4)
                *(float4*)(&bb[j/2]) = *(const float4*)(&sB[cl][tx*TP + j]);
#pragma unroll
            for (int i = 0; i < TM; i++) {
                u64 aa = pk2b(a[i]);
#pragma unroll
                for (int j = 0; j < TP/2; j++) fma2(acc[i][j], aa, bb[j]);
            }
        }
        __syncthreads();
    }
#pragma unroll
    for (int i = 0; i < TM; i++) {
        int m = m0 + ty*TM + i;
        u64 bv2 = BIAS ? pk2b(bias[m]) : 0ull;
        u64 o2[TP/2];
#pragma unroll
        for (int j = 0; j < TP/2; j++) o2[j] = BIAS ? add2(acc[i][j], bv2) : acc[i][j];
        float* yp = Y + ((size_t)n*Mtot + m)*HW + pix0 + tx*TP;
#pragma unroll
        for (int j = 0; j < TP; j += 4)
            *(float4*)(yp + j) = *(float4*)(&o2[j/2]);
    }
}

// ---------------------------------------------------------------------------
// Encoder 3x3 conv as a GEMM (FFMA2 inner):
//   e[o, g] = sum_{m,tap} We[o,m,tap] * tshift(m,g,tap)
// ---------------------------------------------------------------------------
__global__ void k_enc_gemm(const float* __restrict__ t, const float* __restrict__ We,
                           float* __restrict__ e) {
    extern __shared__ float smem[];
    float* sA = smem;           // [(ml*9+tap)*64 + o]
    float* sB = smem + 9216;    // [ml*272 + r*68 + ww]
    int tid = threadIdx.x;      // 128
    int tx = tid & 15;
    int ty = tid >> 4;
    int g0 = blockIdx.x * 128;
    int o0 = blockIdx.y * 64;
    int n  = g0 >> 12;
    int h0 = (g0 & 4095) >> 6;
    const float* tb = t + (size_t)n*CM*HW;

    int s_ml = tid >> 3;
    int s_s  = tid & 7;
    int s_o  = tid & 63;
    int s_hf = tid >> 6;
    int og_a = o0 + s_o;
    bool ook = (og_a < 100);

    u64 acc[8][4];
#pragma unroll
    for (int i = 0; i < 8; i++)
#pragma unroll
        for (int j = 0; j < 4; j++) acc[i][j] = 0ull;

    int rb = tx >> 3;
    int wb = (tx & 7) * 8;

    for (int m0 = 0; m0 < 64; m0 += 16) {
        __syncthreads();
        {
            const float* tc = tb + (size_t)(m0 + s_ml)*HW;
            float* sBc = sB + s_ml*272;
#pragma unroll
            for (int r = 0; r < 4; r++) {
                int hh = h0 + r - 1;
                bool hok = ((unsigned)hh < 64u);
                const float* tr = tc + hh*64;
                float* sr = sBc + r*68;
#pragma unroll
                for (int j = 0; j < 9; j++) {
                    int ww = s_s + 8*j;
                    if (ww < 68) {
                        int wx = ww - 1;
                        sr[ww] = (hok && (unsigned)wx < 64u) ? tr[wx] : 0.f;
                    }
                }
            }
        }
        {
            const float* wrow = ook ? (We + (size_t)og_a*576 + m0*9) : nullptr;
#pragma unroll
            for (int ml = 0; ml < 16; ml++) {
                float* sa = sA + ml*576 + s_o;
#pragma unroll
                for (int tap = 0; tap < 9; tap++) {
                    if ((tap & 1) == s_hf)
                        sa[tap*64] = ook ? wrow[ml*9 + tap] : 0.f;
                }
            }
        }
        __syncthreads();

        for (int ml = 0; ml < 16; ml++) {
#pragma unroll
            for (int tap = 0; tap < 9; tap++) {
                const int di = tap / 3, dj = tap % 3;
                const float* ap = sA + (ml*9 + tap)*64 + ty*8;
                float a[8];
                *(float4*)(a)   = *(const float4*)(ap);
                *(float4*)(a+4) = *(const float4*)(ap+4);
                const float* bp = sB + ml*272 + (rb + di)*68 + wb + dj;
                u64 bb[4];
#pragma unroll
                for (int j = 0; j < 4; j++) bb[j] = pk2(bp[2*j], bp[2*j+1]);
#pragma unroll
                for (int i = 0; i < 8; i++) {
                    u64 aa = pk2b(a[i]);
#pragma unroll
                    for (int j = 0; j < 4; j++) fma2(acc[i][j], aa, bb[j]);
                }
            }
        }
    }

#pragma unroll
    for (int oo = 0; oo < 8; oo++) {
        int o = o0 + ty*8 + oo;
        if (o < 100) {
            float* ep = e + (size_t)o*GTOT + g0 + tx*8;
            *(float4*)(ep)   = *(float4*)(&acc[oo][0]);
            *(float4*)(ep+4) = *(float4*)(&acc[oo][2]);
        }
    }
}

// ---------------------------------------------------------------------------
// Reassembly with fused softmax -> final output (FFMA2 inner, csplit=4).
// Block = (n,h) x csplit(4). Threads (w=64, p=4). 2 chunks of 32 channels.
// ---------------------------------------------------------------------------
__global__ void k_reasm_out(const float* __restrict__ y, const float* __restrict__ e,
                            const float* __restrict__ be, const float* __restrict__ bo,
                            float* __restrict__ out) {
    extern __shared__ float smem[];
    float* sk = smem;              // [k][w][p] : k*256 + w*4 + p
    float* sy = smem + 6400;       // [g][r][ww][4] : g*1360 + r*272 + ww*4 + c4

    int w  = threadIdx.x;
    int cg = threadIdx.y;
    int tid = cg*64 + w;
    int n = blockIdx.x >> 6;
    int h = blockIdx.x & 63;
    int cbase = blockIdx.y * 64;

    int cl = tid >> 3;
    int s  = tid & 7;
    float* syc = sy + (cl >> 2)*5*272 + (cl & 3);

    // ---- fused softmax over k for pixel (n,h,w), sub-pixel p=cg ----
    {
        int g = n*HW + h*64 + w;
        float ek[25];
        float mx = -1e30f;
#pragma unroll
        for (int k = 0; k < 25; k++) {
            ek[k] = e[(size_t)(k*4 + cg)*GTOT + g] + be[k*4 + cg];
            mx = fmaxf(mx, ek[k]);
        }
        float s0 = 0.f;
#pragma unroll
        for (int k = 0; k < 25; k++) {
            ek[k] = __expf(ek[k] - mx);
            s0 += ek[k];
        }
        float inv = 1.f / s0;
#pragma unroll
        for (int k = 0; k < 25; k++) sk[k*256 + w*4 + cg] = ek[k] * inv;
    }

    for (int c0 = cbase; c0 < cbase + 64; c0 += 32) {
        __syncthreads();   // also guards sk visibility on first iteration
        {
            const float* ybase = y + (size_t)(n*CC + c0 + cl)*HW;
#pragma unroll
            for (int r = 0; r < 5; r++) {
                int hh = h + r - 2;
                bool hok = ((unsigned)hh < 64u);
                const float* yr = ybase + hh*64;
                float* syr = syc + r*272;
#pragma unroll
                for (int j = 0; j < 9; j++) {
                    int ww = s + 8*j;
                    if (ww < 68) {
                        int wx = ww - 2;
                        syr[ww*4] = (hok && (unsigned)wx < 64u) ? yr[wx] : 0.f;
                    }
                }
            }
        }
        __syncthreads();

        u64 acc2[8][2];
#pragma unroll
        for (int cc = 0; cc < 8; cc++) { acc2[cc][0] = 0ull; acc2[cc][1] = 0ull; }

        const float* skp = sk + w*4;
        const float* syp = sy + (cg*2)*1360 + w*4;
#pragma unroll
        for (int k = 0; k < 25; k++) {
            const int ki = k / 5, kj = k % 5;
            u64 kp[2];
            *(float4*)(kp) = *(const float4*)(skp + k*256);
            float4 y0 = *(const float4*)(syp + ki*272 + kj*4);
            float4 y1 = *(const float4*)(syp + 1360 + ki*272 + kj*4);
            u64 yb;
            yb = pk2b(y0.x); fma2(acc2[0][0], yb, kp[0]); fma2(acc2[0][1], yb, kp[1]);
            yb = pk2b(y0.y); fma2(acc2[1][0], yb, kp[0]); fma2(acc2[1][1], yb, kp[1]);
            yb = pk2b(y0.z); fma2(acc2[2][0], yb, kp[0]); fma2(acc2[2][1], yb, kp[1]);
            yb = pk2b(y0.w); fma2(acc2[3][0], yb, kp[0]); fma2(acc2[3][1], yb, kp[1]);
            yb = pk2b(y1.x); fma2(acc2[4][0], yb, kp[0]); fma2(acc2[4][1], yb, kp[1]);
            yb = pk2b(y1.y); fma2(acc2[5][0], yb, kp[0]); fma2(acc2[5][1], yb, kp[1]);
            yb = pk2b(y1.z); fma2(acc2[6][0], yb, kp[0]); fma2(acc2[6][1], yb, kp[1]);
            yb = pk2b(y1.w); fma2(acc2[7][0], yb, kp[0]); fma2(acc2[7][1], yb, kp[1]);
        }

#pragma unroll
        for (int cc = 0; cc < 8; cc++) {
            int c = c0 + cg*8 + cc;
            u64 b2 = pk2b(bo[c]);
            u64 r0 = add2(acc2[cc][0], b2);
            u64 r1 = add2(acc2[cc][1], b2);
            float* op = out + ((size_t)(n*CC + c) * 128 + 2*h) * 128 + 2*w;
            *(float2*)(op)       = *(float2*)(&r0);
            *(float2*)(op + 128) = *(float2*)(&r1);
        }
    }
}

// ---------------------------------------------------------------------------
extern "C" void kernel_launch(void* const* d_in, const int* in_sizes, int n_in,
                              void* d_out, int out_size) {
    const float* x   = (const float*)d_in[0];
    const float* Wd  = (const float*)d_in[1];
    const float* bd  = (const float*)d_in[2];
    const float* We  = (const float*)d_in[3];
    const float* be  = (const float*)d_in[4];
    const float* Wo  = (const float*)d_in[5];
    const float* bo  = (const float*)d_in[6];
    float* out = (float*)d_out;

    float *t, *e, *y;
    cudaGetSymbolAddress((void**)&t, g_t);
    cudaGetSymbolAddress((void**)&e, g_e);
    cudaGetSymbolAddress((void**)&y, g_y);

    cudaFuncSetAttribute(k_enc_gemm,  cudaFuncAttributeMaxDynamicSharedMemorySize, 54272);
    cudaFuncSetAttribute(k_reasm_out, cudaFuncAttributeMaxDynamicSharedMemorySize, 69120);

    // t = Wd*x + bd   (64 x 256 x 16384)
    k_gemm<64,8,8,true><<<dim3(32,1,NN), 128>>>(x, Wd, bd, t);
    // e = conv3x3(t)  (raw, softmax fused into reassembly)
    k_enc_gemm<<<dim3(128,2), 128, 54272>>>(t, We, e);
    // y = Wo*x        (256 x 256 x 16384)
    k_gemm<128,8,8,false><<<dim3(32,2,NN), 256>>>(x, Wo, nullptr, y);
    // out = reasm(y, softmax(e+be)) + bo
    k_reasm_out<<<dim3(256,4), dim3(64,4), 69120>>>(y, e, be, bo, out);
}

// round 9
// speedup vs baseline: 3.0740x; 1.2771x over previous
#include <cuda_runtime.h>
#include <cuda_bf16.h>

#define NN 4
#define CC 256
#define HH 64
#define WW 64
#define CM 64
#define K2 25
#define HW (HH*WW)          // 4096
#define GTOT (NN*HW)        // 16384 total low-res pixels

typedef unsigned long long u64;
typedef unsigned int u32;

// ---- packed fp32x2 helpers (FFMA2) ----
__device__ __forceinline__ u64 pk2b(float v) {
    u64 r; asm("mov.b64 %0, {%1, %1};" : "=l"(r) : "f"(v)); return r;
}
__device__ __forceinline__ u64 pk2(float lo, float hi) {
    u64 r; asm("mov.b64 %0, {%1, %2};" : "=l"(r) : "f"(lo), "f"(hi)); return r;
}
__device__ __forceinline__ void fma2(u64 &d, u64 a, u64 b) {
    asm("fma.rn.f32x2 %0, %1, %2, %0;" : "+l"(d) : "l"(a), "l"(b));
}
__device__ __forceinline__ u64 add2(u64 a, u64 b) {
    u64 r; asm("add.rn.f32x2 %0, %1, %2;" : "=l"(r) : "l"(a), "l"(b)); return r;
}

// ---- tensor-core helpers ----
__device__ __forceinline__ u32 smaddr(const void* p) {
    return (u32)__cvta_generic_to_shared(p);
}
__device__ __forceinline__ void ldmA(u32 a, u32 r[4]) {
    asm volatile("ldmatrix.sync.aligned.m8n8.x4.shared.b16 {%0,%1,%2,%3},[%4];"
        : "=r"(r[0]), "=r"(r[1]), "=r"(r[2]), "=r"(r[3]) : "r"(a));
}
__device__ __forceinline__ void ldmBT(u32 a, u32 r[4]) {
    asm volatile("ldmatrix.sync.aligned.m8n8.x4.trans.shared.b16 {%0,%1,%2,%3},[%4];"
        : "=r"(r[0]), "=r"(r[1]), "=r"(r[2]), "=r"(r[3]) : "r"(a));
}
__device__ __forceinline__ void mma16816(float d[4], const u32 a[4], const u32 b[2]) {
    asm volatile("mma.sync.aligned.m16n8k16.row.col.f32.bf16.bf16.f32 "
        "{%0,%1,%2,%3},{%4,%5,%6,%7},{%8,%9},{%0,%1,%2,%3};"
        : "+f"(d[0]), "+f"(d[1]), "+f"(d[2]), "+f"(d[3])
        : "r"(a[0]), "r"(a[1]), "r"(a[2]), "r"(a[3]), "r"(b[0]), "r"(b[1]));
}

// Scratch (device globals; allocation-free per harness rules)
__device__ float g_t[NN*CM*HW];                 // fp32 down features
__device__ float g_e[100*GTOT];                 // raw encoder conv output [o][g]
__device__ float g_y[NN*CC*HW];                 // y = Wo * x (low-res)
__device__ __nv_bfloat16 g_xh[NN*CC*HW];        // x split hi
__device__ __nv_bfloat16 g_xl[NN*CC*HW];        // x split lo
__device__ __nv_bfloat16 g_woh[256*256], g_wol[256*256];
__device__ __nv_bfloat16 g_wdh[64*256],  g_wdl[64*256];

// ---------------------------------------------------------------------------
// Split fp32 -> (hi, lo) bf16.  n4 = element count / 4.
// ---------------------------------------------------------------------------
__global__ void k_split(const float* __restrict__ src, __nv_bfloat16* __restrict__ h,
                        __nv_bfloat16* __restrict__ l, int n4) {
    int i = blockIdx.x * blockDim.x + threadIdx.x;
    if (i >= n4) return;
    float4 v = ((const float4*)src)[i];
    __nv_bfloat16 h0 = __float2bfloat16(v.x);
    __nv_bfloat16 h1 = __float2bfloat16(v.y);
    __nv_bfloat16 h2 = __float2bfloat16(v.z);
    __nv_bfloat16 h3 = __float2bfloat16(v.w);
    __nv_bfloat16 l0 = __float2bfloat16(v.x - __bfloat162float(h0));
    __nv_bfloat16 l1 = __float2bfloat16(v.y - __bfloat162float(h1));
    __nv_bfloat16 l2 = __float2bfloat16(v.z - __bfloat162float(h2));
    __nv_bfloat16 l3 = __float2bfloat16(v.w - __bfloat162float(h3));
    ((__nv_bfloat162*)h)[i*2]   = __nv_bfloat162(h0, h1);
    ((__nv_bfloat162*)h)[i*2+1] = __nv_bfloat162(h2, h3);
    ((__nv_bfloat162*)l)[i*2]   = __nv_bfloat162(l0, l1);
    ((__nv_bfloat162*)l)[i*2+1] = __nv_bfloat162(l2, l3);
}

// ---------------------------------------------------------------------------
// Tensor-core GEMM with 2-term bf16 split:
//   Y[n,m,pix] = sum_c W[m,c]*X[n,c,pix] (+b[m]),  W,X pre-split hi/lo bf16.
// Block tile BM x 128 pixels; warp tile 64 x 32; K-chunk 32.
// acc += Ah*Bh + Al*Bh + Ah*Bl  (Al*Bl dropped, ~2^-18 relative)
// ---------------------------------------------------------------------------
template<int BM, bool BIAS>
__global__ void k_mma(const __nv_bfloat16* __restrict__ Xh, const __nv_bfloat16* __restrict__ Xl,
                      const __nv_bfloat16* __restrict__ Wh, const __nv_bfloat16* __restrict__ Wl,
                      const float* __restrict__ bias, float* __restrict__ Y, int Mtot) {
    constexpr int WMW = BM/64;            // warps along m
    constexpr int NT  = 32*WMW*4;         // threads (4 warps along n)
    constexpr int SAS = 40;               // sA stride (bf16), conflict-free pad
    constexpr int SBS = 136;              // sB stride (bf16)
    __shared__ __nv_bfloat16 sAh[BM*SAS], sAl[BM*SAS];
    __shared__ __nv_bfloat16 sBh[32*SBS], sBl[32*SBS];

    int tid = threadIdx.x, lane = tid & 31, warp = tid >> 5;
    int wx = warp & 3, wy = warp >> 2;
    int pix0 = blockIdx.x * 128;
    int m0   = blockIdx.y * BM;
    int n    = blockIdx.z;
    const __nv_bfloat16* xbh = Xh + (size_t)n*CC*HW + pix0;
    const __nv_bfloat16* xbl = Xl + (size_t)n*CC*HW + pix0;

    float acc[4][4][4];
#pragma unroll
    for (int a = 0; a < 4; a++)
#pragma unroll
        for (int b = 0; b < 4; b++)
#pragma unroll
            for (int c = 0; c < 4; c++) acc[a][b][c] = 0.f;

    // ldmatrix lane-address components
    int aRow = lane & 15;
    int aCol = (lane >> 4) * 8;
    int bRow = (lane & 7) + ((lane >> 3) & 1) * 8;
    int bCol = (lane >> 4) * 8;

    for (int c0 = 0; c0 < 256; c0 += 32) {
        __syncthreads();
        // stage A (weights): BM x 32, 16B chunks
#pragma unroll
        for (int i = 0; i < BM*4/NT; i++) {
            int ch = i*NT + tid;
            int row = ch >> 2, k8 = (ch & 3) * 8;
            *(uint4*)(sAh + row*SAS + k8) = *(const uint4*)(Wh + (size_t)(m0+row)*256 + c0 + k8);
            *(uint4*)(sAl + row*SAS + k8) = *(const uint4*)(Wl + (size_t)(m0+row)*256 + c0 + k8);
        }
        // stage B (pixels): 32 x 128, 16B chunks
#pragma unroll
        for (int i = 0; i < 512/NT; i++) {
            int ch = i*NT + tid;
            int row = ch >> 4, n8 = (ch & 15) * 8;
            *(uint4*)(sBh + row*SBS + n8) = *(const uint4*)(xbh + (size_t)(c0+row)*HW + n8);
            *(uint4*)(sBl + row*SBS + n8) = *(const uint4*)(xbl + (size_t)(c0+row)*HW + n8);
        }
        __syncthreads();

#pragma unroll
        for (int ks = 0; ks < 2; ks++) {
            int k0 = ks * 16;
            u32 Ah[4][4], Al[4][4], Bh[2][4], Bl[2][4];
#pragma unroll
            for (int mi = 0; mi < 4; mi++) {
                int row = wy*64 + mi*16 + aRow;
                ldmA(smaddr(sAh + row*SAS + k0 + aCol), Ah[mi]);
                ldmA(smaddr(sAl + row*SAS + k0 + aCol), Al[mi]);
            }
#pragma unroll
            for (int g = 0; g < 2; g++) {
                int col = wx*32 + g*16 + bCol;
                ldmBT(smaddr(sBh + (k0 + bRow)*SBS + col), Bh[g]);
                ldmBT(smaddr(sBl + (k0 + bRow)*SBS + col), Bl[g]);
            }
#pragma unroll
            for (int mi = 0; mi < 4; mi++)
#pragma unroll
                for (int ni = 0; ni < 4; ni++) {
                    const u32* bh = &Bh[ni>>1][(ni&1)*2];
                    const u32* bl = &Bl[ni>>1][(ni&1)*2];
                    mma16816(acc[mi][ni], Ah[mi], bh);
                    mma16816(acc[mi][ni], Al[mi], bh);
                    mma16816(acc[mi][ni], Ah[mi], bl);
                }
        }
    }

    // epilogue: d0,d1 at (row, col..col+1), d2,d3 at (row+8)
#pragma unroll
    for (int mi = 0; mi < 4; mi++) {
#pragma unroll
        for (int half = 0; half < 2; half++) {
            int m = m0 + wy*64 + mi*16 + (lane >> 2) + half*8;
            float bv = BIAS ? bias[m] : 0.f;
            float* yp = Y + ((size_t)n*Mtot + m)*HW + pix0 + wx*32 + (lane & 3)*2;
#pragma unroll
            for (int ni = 0; ni < 4; ni++) {
                float2 v = make_float2(acc[mi][ni][half*2] + bv, acc[mi][ni][half*2+1] + bv);
                *(float2*)(yp + ni*8) = v;
            }
        }
    }
}

// ---------------------------------------------------------------------------
// Encoder 3x3 conv as a GEMM (fp32 FFMA2) -- unchanged from round 8.
// ---------------------------------------------------------------------------
__global__ void k_enc_gemm(const float* __restrict__ t, const float* __restrict__ We,
                           float* __restrict__ e) {
    extern __shared__ float smem[];
    float* sA = smem;           // [(ml*9+tap)*64 + o]
    float* sB = smem + 9216;    // [ml*272 + r*68 + ww]
    int tid = threadIdx.x;      // 128
    int tx = tid & 15;
    int ty = tid >> 4;
    int g0 = blockIdx.x * 128;
    int o0 = blockIdx.y * 64;
    int n  = g0 >> 12;
    int h0 = (g0 & 4095) >> 6;
    const float* tb = t + (size_t)n*CM*HW;

    int s_ml = tid >> 3;
    int s_s  = tid & 7;
    int s_o  = tid & 63;
    int s_hf = tid >> 6;
    int og_a = o0 + s_o;
    bool ook = (og_a < 100);

    u64 acc[8][4];
#pragma unroll
    for (int i = 0; i < 8; i++)
#pragma unroll
        for (int j = 0; j < 4; j++) acc[i][j] = 0ull;

    int rb = tx >> 3;
    int wb = (tx & 7) * 8;

    for (int m0 = 0; m0 < 64; m0 += 16) {
        __syncthreads();
        {
            const float* tc = tb + (size_t)(m0 + s_ml)*HW;
            float* sBc = sB + s_ml*272;
#pragma unroll
            for (int r = 0; r < 4; r++) {
                int hh = h0 + r - 1;
                bool hok = ((unsigned)hh < 64u);
                const float* tr = tc + hh*64;
                float* sr = sBc + r*68;
#pragma unroll
                for (int j = 0; j < 9; j++) {
                    int ww = s_s + 8*j;
                    if (ww < 68) {
                        int wx2 = ww - 1;
                        sr[ww] = (hok && (unsigned)wx2 < 64u) ? tr[wx2] : 0.f;
                    }
                }
            }
        }
        {
            const float* wrow = ook ? (We + (size_t)og_a*576 + m0*9) : nullptr;
#pragma unroll
            for (int ml = 0; ml < 16; ml++) {
                float* sa = sA + ml*576 + s_o;
#pragma unroll
                for (int tap = 0; tap < 9; tap++) {
                    if ((tap & 1) == s_hf)
                        sa[tap*64] = ook ? wrow[ml*9 + tap] : 0.f;
                }
            }
        }
        __syncthreads();

        for (int ml = 0; ml < 16; ml++) {
#pragma unroll
            for (int tap = 0; tap < 9; tap++) {
                const int di = tap / 3, dj = tap % 3;
                const float* ap = sA + (ml*9 + tap)*64 + ty*8;
                float a[8];
                *(float4*)(a)   = *(const float4*)(ap);
                *(float4*)(a+4) = *(const float4*)(ap+4);
                const float* bp = sB + ml*272 + (rb + di)*68 + wb + dj;
                u64 bb[4];
#pragma unroll
                for (int j = 0; j < 4; j++) bb[j] = pk2(bp[2*j], bp[2*j+1]);
#pragma unroll
                for (int i = 0; i < 8; i++) {
                    u64 aa = pk2b(a[i]);
#pragma unroll
                    for (int j = 0; j < 4; j++) fma2(acc[i][j], aa, bb[j]);
                }
            }
        }
    }

#pragma unroll
    for (int oo = 0; oo < 8; oo++) {
        int o = o0 + ty*8 + oo;
        if (o < 100) {
            float* ep = e + (size_t)o*GTOT + g0 + tx*8;
            *(float4*)(ep)   = *(float4*)(&acc[oo][0]);
            *(float4*)(ep+4) = *(float4*)(&acc[oo][2]);
        }
    }
}

// ---------------------------------------------------------------------------
// Reassembly with fused softmax -> final output (unchanged from round 8).
// ---------------------------------------------------------------------------
__global__ void k_reasm_out(const float* __restrict__ y, const float* __restrict__ e,
                            const float* __restrict__ be, const float* __restrict__ bo,
                            float* __restrict__ out) {
    extern __shared__ float smem[];
    float* sk = smem;              // [k][w][p]
    float* sy = smem + 6400;       // [g][r][ww][4]

    int w  = threadIdx.x;
    int cg = threadIdx.y;
    int tid = cg*64 + w;
    int n = blockIdx.x >> 6;
    int h = blockIdx.x & 63;
    int cbase = blockIdx.y * 64;

    int cl = tid >> 3;
    int s  = tid & 7;
    float* syc = sy + (cl >> 2)*5*272 + (cl & 3);

    {
        int g = n*HW + h*64 + w;
        float ek[25];
        float mx = -1e30f;
#pragma unroll
        for (int k = 0; k < 25; k++) {
            ek[k] = e[(size_t)(k*4 + cg)*GTOT + g] + be[k*4 + cg];
            mx = fmaxf(mx, ek[k]);
        }
        float s0 = 0.f;
#pragma unroll
        for (int k = 0; k < 25; k++) {
            ek[k] = __expf(ek[k] - mx);
            s0 += ek[k];
        }
        float inv = 1.f / s0;
#pragma unroll
        for (int k = 0; k < 25; k++) sk[k*256 + w*4 + cg] = ek[k] * inv;
    }

    for (int c0 = cbase; c0 < cbase + 64; c0 += 32) {
        __syncthreads();
        {
            const float* ybase = y + (size_t)(n*CC + c0 + cl)*HW;
#pragma unroll
            for (int r = 0; r < 5; r++) {
                int hh = h + r - 2;
                bool hok = ((unsigned)hh < 64u);
                const float* yr = ybase + hh*64;
                float* syr = syc + r*272;
#pragma unroll
                for (int j = 0; j < 9; j++) {
                    int ww = s + 8*j;
                    if (ww < 68) {
                        int wx = ww - 2;
                        syr[ww*4] = (hok && (unsigned)wx < 64u) ? yr[wx] : 0.f;
                    }
                }
            }
        }
        __syncthreads();

        u64 acc2[8][2];
#pragma unroll
        for (int cc = 0; cc < 8; cc++) { acc2[cc][0] = 0ull; acc2[cc][1] = 0ull; }

        const float* skp = sk + w*4;
        const float* syp = sy + (cg*2)*1360 + w*4;
#pragma unroll
        for (int k = 0; k < 25; k++) {
            const int ki = k / 5, kj = k % 5;
            u64 kp[2];
            *(float4*)(kp) = *(const float4*)(skp + k*256);
            float4 y0 = *(const float4*)(syp + ki*272 + kj*4);
            float4 y1 = *(const float4*)(syp + 1360 + ki*272 + kj*4);
            u64 yb;
            yb = pk2b(y0.x); fma2(acc2[0][0], yb, kp[0]); fma2(acc2[0][1], yb, kp[1]);
            yb = pk2b(y0.y); fma2(acc2[1][0], yb, kp[0]); fma2(acc2[1][1], yb, kp[1]);
            yb = pk2b(y0.z); fma2(acc2[2][0], yb, kp[0]); fma2(acc2[2][1], yb, kp[1]);
            yb = pk2b(y0.w); fma2(acc2[3][0], yb, kp[0]); fma2(acc2[3][1], yb, kp[1]);
            yb = pk2b(y1.x); fma2(acc2[4][0], yb, kp[0]); fma2(acc2[4][1], yb, kp[1]);
            yb = pk2b(y1.y); fma2(acc2[5][0], yb, kp[0]); fma2(acc2[5][1], yb, kp[1]);
            yb = pk2b(y1.z); fma2(acc2[6][0], yb, kp[0]); fma2(acc2[6][1], yb, kp[1]);
            yb = pk2b(y1.w); fma2(acc2[7][0], yb, kp[0]); fma2(acc2[7][1], yb, kp[1]);
        }

#pragma unroll
        for (int cc = 0; cc < 8; cc++) {
            int c = c0 + cg*8 + cc;
            u64 b2 = pk2b(bo[c]);
            u64 r0 = add2(acc2[cc][0], b2);
            u64 r1 = add2(acc2[cc][1], b2);
            float* op = out + ((size_t)(n*CC + c) * 128 + 2*h) * 128 + 2*w;
            *(float2*)(op)       = *(float2*)(&r0);
            *(float2*)(op + 128) = *(float2*)(&r1);
        }
    }
}

// ---------------------------------------------------------------------------
extern "C" void kernel_launch(void* const* d_in, const int* in_sizes, int n_in,
                              void* d_out, int out_size) {
    const float* x   = (const float*)d_in[0];
    const float* Wd  = (const float*)d_in[1];
    const float* bd  = (const float*)d_in[2];
    const float* We  = (const float*)d_in[3];
    const float* be  = (const float*)d_in[4];
    const float* Wo  = (const float*)d_in[5];
    const float* bo  = (const float*)d_in[6];
    float* out = (float*)d_out;

    float *t, *e, *y;
    __nv_bfloat16 *xh, *xl, *woh, *wol, *wdh, *wdl;
    cudaGetSymbolAddress((void**)&t,   g_t);
    cudaGetSymbolAddress((void**)&e,   g_e);
    cudaGetSymbolAddress((void**)&y,   g_y);
    cudaGetSymbolAddress((void**)&xh,  g_xh);
    cudaGetSymbolAddress((void**)&xl,  g_xl);
    cudaGetSymbolAddress((void**)&woh, g_woh);
    cudaGetSymbolAddress((void**)&wol, g_wol);
    cudaGetSymbolAddress((void**)&wdh, g_wdh);
    cudaGetSymbolAddress((void**)&wdl, g_wdl);

    cudaFuncSetAttribute(k_enc_gemm,  cudaFuncAttributeMaxDynamicSharedMemorySize, 54272);
    cudaFuncSetAttribute(k_reasm_out, cudaFuncAttributeMaxDynamicSharedMemorySize, 69120);

    // splits
    k_split<<<4096, 256>>>(x,  xh,  xl,  NN*CC*HW/4);
    k_split<<<64,   256>>>(Wo, woh, wol, 256*256/4);
    k_split<<<16,   256>>>(Wd, wdh, wdl, 64*256/4);
    // t = Wd*x + bd   (tensor core)
    k_mma<64, true><<<dim3(32, 1, NN), 128>>>(xh, xl, wdh, wdl, bd, t, CM);
    // e = conv3x3(t)  (fp32; softmax fused into reassembly)
    k_enc_gemm<<<dim3(128, 2), 128, 54272>>>(t, We, e);
    // y = Wo*x        (tensor core)
    k_mma<128, false><<<dim3(32, 2, NN), 256>>>(xh, xl, woh, wol, nullptr, y, CC);
    // out = reasm(y, softmax(e+be)) + bo
    k_reasm_out<<<dim3(256, 4), dim3(64, 4), 69120>>>(y, e, be, bo, out);
}